// round 15
// baseline (speedup 1.0000x reference)
#include <cuda_runtime.h>
#include <cuda_bf16.h>

#define NB    8
#define NC    512
#define NPIX  4096      // 64*64
#define NCLS  19
#define TGT   512
#define NSPLIT 32
#define CSPAN (NC/NSPLIT)   // 16
#define K3_T  256
#define PXB   (K3_T*2)      // 512 pixels per K3 block
#define NTILE (NPIX/PXB)    // 8
#define NROW  (NB*NC*2)     // 8192 channel-rows (S then T)

// ---------------- device scratch (static, no allocations) ----------------
__device__ unsigned char g_lab[NB*NPIX];
__device__ float g_cnt [NB*NCLS];
__device__ float g_sumS[NB*NC*NCLS];
__device__ float g_sumT[NB*NC*NCLS];
__device__ float g_nsqS[NB*NCLS];
__device__ float g_nsqT[NB*NCLS];
__device__ float g_accum[4][NB*NPIX];   // dotS,fsqS,dotT,fsqT (atomics)
__device__ float g_blockred[128];

// ---- K0: labels+histogram (blocks 0..7); zero accum+nsq (blocks 8..40) ----
__global__ void k_prep(const int* __restrict__ tgt) {
    int blk = blockIdx.x;
    if (blk >= NB) {
        if (blk == NB + 32) {        // zero nsq (2*152 floats)
            int i = threadIdx.x;
            if (i < NB*NCLS) { g_nsqS[i] = 0.f; g_nsqT[i] = 0.f; }
            return;
        }
        // zero g_accum: 32 blocks * 256 threads * 4 float4 = 512 KB
        int z = (blk - NB)*256 + threadIdx.x;      // 0..8191
        float4* p = (float4*)g_accum;               // 32768 float4 total
        #pragma unroll
        for (int j = 0; j < 4; j++) p[z*4 + j] = make_float4(0.f,0.f,0.f,0.f);
        return;
    }
    int b = blk;
    __shared__ int hist[NCLS];
    if (threadIdx.x < NCLS) hist[threadIdx.x] = 0;
    __syncthreads();
    for (int n = threadIdx.x; n < NPIX; n += blockDim.x) {
        int h = n >> 6, w = n & 63;
        int k = tgt[b*TGT*TGT + (h*8)*TGT + (w*8)];   // nearest: idx*8
        unsigned char lab = (k >= 0 && k < NCLS) ? (unsigned char)k : (unsigned char)255;
        g_lab[b*NPIX + n] = lab;
        if (lab != 255) atomicAdd(&hist[k], 1);
    }
    __syncthreads();
    if (threadIdx.x < NCLS) g_cnt[b*NCLS + threadIdx.x] = (float)hist[threadIdx.x];
}

// ---------------- K1: warp-per-channel class sums, lane-private bins ------
// 4 warps/block -> 2048 blocks (13.8/SM, ~7% wave tail). Epilogue also
// accumulates nsq[b][k] += s_k^2 via REDG (replaces k_stats kernel).
__global__ __launch_bounds__(128) void k_classsum(const float* __restrict__ S,
                                                  const float* __restrict__ T) {
    __shared__ float bins[4][NCLS+1][32];   // slot NCLS = trash for invalid labels
    int t    = threadIdx.x;
    int w    = t >> 5;
    int lane = t & 31;

    int r = blockIdx.x * 4 + w;          // 0..NROW-1
    int tensor = r >> 12;                // 0 = S, 1 = T
    int bc = r & (NB*NC - 1);
    int b  = bc >> 9;
    const float* F = tensor ? T : S;
    float* outp    = tensor ? g_sumT : g_sumS;
    float* nsqp    = tensor ? g_nsqT : g_nsqS;

    #pragma unroll
    for (int k = 0; k <= NCLS; k++) bins[w][k][lane] = 0.f;

    const float4* row = (const float4*)(F + (size_t)bc * NPIX);
    const uchar4* lb  = (const uchar4*)&g_lab[b*NPIX];
    float* mb = &bins[w][0][lane];

    #pragma unroll 4
    for (int i = lane; i < NPIX/4; i += 32) {
        float4 v = row[i];
        uchar4 l = lb[i];
        int kx = l.x < NCLS ? l.x : NCLS;
        int ky = l.y < NCLS ? l.y : NCLS;
        int kz = l.z < NCLS ? l.z : NCLS;
        int kw = l.w < NCLS ? l.w : NCLS;
        mb[32*kx] += v.x;
        mb[32*ky] += v.y;
        mb[32*kz] += v.z;
        mb[32*kw] += v.w;
    }
    __syncwarp();

    size_t ob = (size_t)bc * NCLS;
    #pragma unroll
    for (int k = 0; k < NCLS; k++) {
        float v = bins[w][k][lane];
        #pragma unroll
        for (int o = 16; o > 0; o >>= 1) v += __shfl_down_sync(0xFFFFFFFFu, v, o);
        if (lane == 0) {
            outp[ob + k] = v;
            atomicAdd(&nsqp[b*NCLS + k], v*v);
        }
    }
}

// ---------------- K3: main pass — per-pixel ||f||^2 and f·sums[class] -----
// NSPLIT=32 -> grid 2048 (13.8/SM) for better wave balance. Epilogue: REDG
// atomics into L2-resident accumulators.
__global__ __launch_bounds__(K3_T) void k_main(const float* __restrict__ S,
                                               const float* __restrict__ T) {
    int tile = blockIdx.x;   // 0..NTILE-1
    int b    = blockIdx.y;   // 0..7
    int sp   = blockIdx.z;   // 0..NSPLIT-1
    __shared__ float shS[CSPAN*NCLS];   // 16*19 = 304 floats
    __shared__ float shT[CSPAN*NCLS];
    int t = threadIdx.x;
    int c0 = sp*CSPAN;

    for (int i = t; i < CSPAN*NCLS; i += K3_T) {   // 304 elements, 2 rounds
        shS[i] = g_sumS[((size_t)(b*NC + c0))*NCLS + i];
        shT[i] = g_sumT[((size_t)(b*NC + c0))*NCLS + i];
    }
    int px = tile*PXB + 2*t;
    unsigned char lx = g_lab[b*NPIX + px];
    unsigned char ly = g_lab[b*NPIX + px + 1];
    int k0 = (lx < NCLS) ? lx : 0;   // dot unused for invalid labels
    int k1 = (ly < NCLS) ? ly : 0;
    __syncthreads();

    const float2* pS = (const float2*)(S + ((size_t)(b*NC + c0))*NPIX + px);
    const float2* pT = (const float2*)(T + ((size_t)(b*NC + c0))*NPIX + px);

    float dS0=0,dS1=0, fS0=0,fS1=0;
    float dT0=0,dT1=0, fT0=0,fT1=0;
    #pragma unroll
    for (int c = 0; c < CSPAN; c++) {
        float2 vS = pS[c*(NPIX/2)];
        float2 vT = pT[c*(NPIX/2)];
        float sA = shS[c*NCLS + k0], sB = shS[c*NCLS + k1];
        float tA = shT[c*NCLS + k0], tB = shT[c*NCLS + k1];
        fS0 += vS.x*vS.x;  dS0 += vS.x*sA;
        fS1 += vS.y*vS.y;  dS1 += vS.y*sB;
        fT0 += vT.x*vT.x;  dT0 += vT.x*tA;
        fT1 += vT.y*vT.y;  dT1 += vT.y*tB;
    }
    int gi = b*NPIX + px;
    atomicAdd(&g_accum[0][gi],   dS0);
    atomicAdd(&g_accum[0][gi+1], dS1);
    atomicAdd(&g_accum[1][gi],   fS0);
    atomicAdd(&g_accum[1][gi+1], fS1);
    atomicAdd(&g_accum[2][gi],   dT0);
    atomicAdd(&g_accum[2][gi+1], dT1);
    atomicAdd(&g_accum[3][gi],   fT0);
    atomicAdd(&g_accum[3][gi+1], fT1);
}

// ---------------- K4: cosine sims + per-block MSE partial (L2 reads) ------
__global__ void k_final() {
    int t = threadIdx.x;
    int gi = blockIdx.x*256 + t;   // 128 blocks * 256 = 32768 pixels
    float dS = g_accum[0][gi];
    float fS = g_accum[1][gi];
    float dT = g_accum[2][gi];
    float fT = g_accum[3][gi];
    int b = gi >> 12;
    int k = g_lab[gi];
    float pS_, pT_;
    if (k < NCLS) {
        float cnt = g_cnt[b*NCLS + k];
        float inv = 1.f/(cnt + 1e-6f);
        float nfS = sqrtf(fS);
        float nmS = sqrtf(g_nsqS[b*NCLS + k]) * inv;
        pS_ = (dS*inv) / (fmaxf(nfS, 1e-8f) * fmaxf(nmS, 1e-8f));
        float nfT = sqrtf(fT);
        float nmT = sqrtf(g_nsqT[b*NCLS + k]) * inv;
        pT_ = (dT*inv) / (fmaxf(nfT, 1e-8f) * fmaxf(nmT, 1e-8f));
    } else {
        // invalid label: center = f  ->  cos(f, f)
        float nfS = fmaxf(sqrtf(fS), 1e-8f); pS_ = fS/(nfS*nfS);
        float nfT = fmaxf(sqrtf(fT), 1e-8f); pT_ = fT/(nfT*nfT);
    }
    float d = pS_ - pT_;
    float v = d*d;
    #pragma unroll
    for (int o = 16; o > 0; o >>= 1) v += __shfl_down_sync(0xFFFFFFFFu, v, o);
    __shared__ float sw[8];
    if ((t & 31) == 0) sw[t >> 5] = v;
    __syncthreads();
    if (t == 0) {
        float a = 0.f;
        #pragma unroll
        for (int w = 0; w < 8; w++) a += sw[w];
        g_blockred[blockIdx.x] = a;
    }
}

// ---------------- K5: final deterministic reduction to scalar -------------
__global__ void k_out(float* __restrict__ out) {
    int t = threadIdx.x;   // 128 threads
    float v = g_blockred[t];
    #pragma unroll
    for (int o = 16; o > 0; o >>= 1) v += __shfl_down_sync(0xFFFFFFFFu, v, o);
    __shared__ float s[4];
    if ((t & 31) == 0) s[t >> 5] = v;
    __syncthreads();
    if (t == 0) out[0] = (s[0] + s[1] + s[2] + s[3]) * (1.f/32768.f);
}

extern "C" void kernel_launch(void* const* d_in, const int* in_sizes, int n_in,
                              void* d_out, int out_size) {
    const float* S   = (const float*)d_in[0];
    const float* T   = (const float*)d_in[1];
    const int*   tgt = (const int*)d_in[2];
    float* out = (float*)d_out;

    k_prep    <<<NB + 33, 256>>>(tgt);
    k_classsum<<<NROW/4, 128>>>(S, T);
    k_main    <<<dim3(NTILE, NB, NSPLIT), K3_T>>>(S, T);
    k_final   <<<128, 256>>>();
    k_out     <<<1, 128>>>(out);
}

// round 16
// speedup vs baseline: 1.6303x; 1.6303x over previous
#include <cuda_runtime.h>
#include <cuda_bf16.h>

#define NB    8
#define NC    512
#define NPIX  4096      // 64*64
#define NCLS  19
#define TGT   512
#define NSPLIT 16
#define CSPAN (NC/NSPLIT)   // 32
#define NROW  (NB*NC*2)     // 8192 channel-rows

#define G_K1   1024          // producer blocks (8 rows each, batch-major)
#define G_NSQ  8
#define G_MAIN 1024          // consumer blocks (128 per batch)
#define G_ALL  (G_K1 + G_NSQ + G_MAIN)

// ---------------- device scratch (static, no allocations) ----------------
__device__ unsigned char g_lab[NB*NPIX];
__device__ float g_cnt [NB*NCLS];
__device__ float g_sumS[NB*NC*NCLS];
__device__ float g_sumT[NB*NC*NCLS];
__device__ float g_nsqS[NB*NCLS];
__device__ float g_nsqT[NB*NCLS];
__device__ float g_accum[4][NB*NPIX];   // dotS,fsqS,dotT,fsqT (atomics)
__device__ float g_blockred[128];
__device__ int   g_done[NB];            // per-batch producer counters

// ---- K0: labels+histogram (blocks 0..7); zero accum (8..39); done (40) ----
__global__ void k_prep(const int* __restrict__ tgt) {
    int blk = blockIdx.x;
    if (blk >= NB) {
        if (blk == NB + 32) {
            if (threadIdx.x < NB) g_done[threadIdx.x] = 0;
            return;
        }
        int z = (blk - NB)*256 + threadIdx.x;      // 0..8191
        float4* p = (float4*)g_accum;               // 32768 float4 total
        #pragma unroll
        for (int j = 0; j < 4; j++) p[z*4 + j] = make_float4(0.f,0.f,0.f,0.f);
        return;
    }
    int b = blk;
    __shared__ int hist[NCLS];
    if (threadIdx.x < NCLS) hist[threadIdx.x] = 0;
    __syncthreads();
    for (int n = threadIdx.x; n < NPIX; n += blockDim.x) {
        int h = n >> 6, w = n & 63;
        int k = tgt[b*TGT*TGT + (h*8)*TGT + (w*8)];   // nearest: idx*8
        unsigned char lab = (k >= 0 && k < NCLS) ? (unsigned char)k : (unsigned char)255;
        g_lab[b*NPIX + n] = lab;
        if (lab != 255) atomicAdd(&hist[k], 1);
    }
    __syncthreads();
    if (threadIdx.x < NCLS) g_cnt[b*NCLS + threadIdx.x] = (float)hist[threadIdx.x];
}

__device__ __forceinline__ void wait_batch(int b, int t) {
    if (t == 0) {
        while (((volatile int*)g_done)[b] < 128) __nanosleep(128);
        __threadfence();
    }
    __syncthreads();
}

// -------- fused producer/consumer kernel: class sums -> dot/fsq ----------
__global__ __launch_bounds__(256) void k_fused(const float* __restrict__ S,
                                               const float* __restrict__ T) {
    __shared__ float sm[5120];     // K1: bins[8][20][32] | main: shS/shT | nsq: partials
    int t   = threadIdx.x;
    int bid = blockIdx.x;

    if (bid < G_K1) {
        // ---- producer: warp-per-channel class sums (batch-major rows) ----
        int w = t >> 5, lane = t & 31;
        int r = bid*8 + w;               // 0..8191, batch-major
        int b      = r >> 10;
        int cc     = (r & 1023) >> 1;
        int tensor = r & 1;
        int bc = b*NC + cc;
        const float* F = tensor ? T : S;
        float* outp    = tensor ? g_sumT : g_sumS;

        float* mb = &sm[w*640 + lane];   // [w][k][lane], stride 32 -> conflict-free
        #pragma unroll
        for (int k = 0; k <= NCLS; k++) mb[k*32] = 0.f;

        const float4* row = (const float4*)(F + (size_t)bc * NPIX);
        const uchar4* lb  = (const uchar4*)&g_lab[b*NPIX];
        #pragma unroll 4
        for (int i = lane; i < NPIX/4; i += 32) {
            float4 v = row[i];
            uchar4 l = lb[i];
            int kx = l.x < NCLS ? l.x : NCLS;
            int ky = l.y < NCLS ? l.y : NCLS;
            int kz = l.z < NCLS ? l.z : NCLS;
            int kw = l.w < NCLS ? l.w : NCLS;
            mb[32*kx] += v.x;
            mb[32*ky] += v.y;
            mb[32*kz] += v.z;
            mb[32*kw] += v.w;
        }
        __syncwarp();
        size_t ob = (size_t)bc * NCLS;
        #pragma unroll
        for (int k = 0; k < NCLS; k++) {
            float v = sm[w*640 + k*32 + lane];
            #pragma unroll
            for (int o = 16; o > 0; o >>= 1) v += __shfl_down_sync(0xFFFFFFFFu, v, o);
            if (lane == 0) outp[ob + k] = v;
        }
        __syncthreads();
        if (t == 0) { __threadfence(); atomicAdd(&g_done[b], 1); }

    } else if (bid < G_K1 + G_NSQ) {
        // ---- nsq blocks: one per batch, fixed-order partials ----
        int b = bid - G_K1;
        wait_batch(b, t);
        if (t < 2*NCLS*4) {              // 152 threads
            int val = t >> 2, j = t & 3;
            int tensor = (val >= NCLS) ? 1 : 0;
            int k = val - tensor*NCLS;
            const float* gs = tensor ? g_sumT : g_sumS;
            float a = 0.f;
            for (int c = j; c < NC; c += 4) {
                float s = gs[((size_t)(b*NC + c))*NCLS + k];
                a += s*s;
            }
            sm[t] = a;
        }
        __syncthreads();
        if (t < 2*NCLS) {
            float a = (sm[4*t] + sm[4*t+1]) + (sm[4*t+2] + sm[4*t+3]);
            if (t < NCLS) g_nsqS[b*NCLS + t] = a;
            else          g_nsqT[b*NCLS + (t - NCLS)] = a;
        }

    } else {
        // ---- consumer: per-pixel ||f||^2 and f·sums[class] (R13 k_main) ----
        int bidm = bid - (G_K1 + G_NSQ);
        int b    = bidm >> 7;            // slowest -> earliest bids serve b=0
        int sp   = (bidm >> 3) & 15;
        int tile = bidm & 7;
        wait_batch(b, t);

        float* shS = sm;                 // 608
        float* shT = sm + 608;           // 608
        int c0 = sp*CSPAN;
        for (int i = t; i < CSPAN*NCLS; i += 256) {
            shS[i] = g_sumS[((size_t)(b*NC + c0))*NCLS + i];
            shT[i] = g_sumT[((size_t)(b*NC + c0))*NCLS + i];
        }
        int px = tile*512 + 2*t;
        unsigned char lx = g_lab[b*NPIX + px];
        unsigned char ly = g_lab[b*NPIX + px + 1];
        int k0 = (lx < NCLS) ? lx : 0;
        int k1 = (ly < NCLS) ? ly : 0;
        __syncthreads();

        const float2* pS = (const float2*)(S + ((size_t)(b*NC + c0))*NPIX + px);
        const float2* pT = (const float2*)(T + ((size_t)(b*NC + c0))*NPIX + px);

        float dS0=0,dS1=0, fS0=0,fS1=0;
        float dT0=0,dT1=0, fT0=0,fT1=0;
        #pragma unroll 8
        for (int c = 0; c < CSPAN; c++) {
            float2 vS = pS[c*(NPIX/2)];
            float2 vT = pT[c*(NPIX/2)];
            float sA = shS[c*NCLS + k0], sB = shS[c*NCLS + k1];
            float tA = shT[c*NCLS + k0], tB = shT[c*NCLS + k1];
            fS0 += vS.x*vS.x;  dS0 += vS.x*sA;
            fS1 += vS.y*vS.y;  dS1 += vS.y*sB;
            fT0 += vT.x*vT.x;  dT0 += vT.x*tA;
            fT1 += vT.y*vT.y;  dT1 += vT.y*tB;
        }
        int gi = b*NPIX + px;
        atomicAdd(&g_accum[0][gi],   dS0);
        atomicAdd(&g_accum[0][gi+1], dS1);
        atomicAdd(&g_accum[1][gi],   fS0);
        atomicAdd(&g_accum[1][gi+1], fS1);
        atomicAdd(&g_accum[2][gi],   dT0);
        atomicAdd(&g_accum[2][gi+1], dT1);
        atomicAdd(&g_accum[3][gi],   fT0);
        atomicAdd(&g_accum[3][gi+1], fT1);
    }
}

// ---------------- K4: cosine sims + per-block MSE partial -----------------
__global__ void k_final() {
    int t = threadIdx.x;
    int gi = blockIdx.x*256 + t;   // 128 blocks * 256 = 32768 pixels
    float dS = g_accum[0][gi];
    float fS = g_accum[1][gi];
    float dT = g_accum[2][gi];
    float fT = g_accum[3][gi];
    int b = gi >> 12;
    int k = g_lab[gi];
    float pS_, pT_;
    if (k < NCLS) {
        float cnt = g_cnt[b*NCLS + k];
        float inv = 1.f/(cnt + 1e-6f);
        float nfS = sqrtf(fS);
        float nmS = sqrtf(g_nsqS[b*NCLS + k]) * inv;
        pS_ = (dS*inv) / (fmaxf(nfS, 1e-8f) * fmaxf(nmS, 1e-8f));
        float nfT = sqrtf(fT);
        float nmT = sqrtf(g_nsqT[b*NCLS + k]) * inv;
        pT_ = (dT*inv) / (fmaxf(nfT, 1e-8f) * fmaxf(nmT, 1e-8f));
    } else {
        float nfS = fmaxf(sqrtf(fS), 1e-8f); pS_ = fS/(nfS*nfS);
        float nfT = fmaxf(sqrtf(fT), 1e-8f); pT_ = fT/(nfT*nfT);
    }
    float d = pS_ - pT_;
    float v = d*d;
    #pragma unroll
    for (int o = 16; o > 0; o >>= 1) v += __shfl_down_sync(0xFFFFFFFFu, v, o);
    __shared__ float sw[8];
    if ((t & 31) == 0) sw[t >> 5] = v;
    __syncthreads();
    if (t == 0) {
        float a = 0.f;
        #pragma unroll
        for (int w = 0; w < 8; w++) a += sw[w];
        g_blockred[blockIdx.x] = a;
    }
}

// ---------------- K5: final deterministic reduction to scalar -------------
__global__ void k_out(float* __restrict__ out) {
    int t = threadIdx.x;   // 128 threads
    float v = g_blockred[t];
    #pragma unroll
    for (int o = 16; o > 0; o >>= 1) v += __shfl_down_sync(0xFFFFFFFFu, v, o);
    __shared__ float s[4];
    if ((t & 31) == 0) s[t >> 5] = v;
    __syncthreads();
    if (t == 0) out[0] = (s[0] + s[1] + s[2] + s[3]) * (1.f/32768.f);
}

extern "C" void kernel_launch(void* const* d_in, const int* in_sizes, int n_in,
                              void* d_out, int out_size) {
    const float* S   = (const float*)d_in[0];
    const float* T   = (const float*)d_in[1];
    const int*   tgt = (const int*)d_in[2];
    float* out = (float*)d_out;

    k_prep <<<NB + 33, 256>>>(tgt);
    k_fused<<<G_ALL, 256>>>(S, T);
    k_final<<<128, 256>>>();
    k_out  <<<1, 128>>>(out);
}

// round 17
// speedup vs baseline: 1.6850x; 1.0335x over previous
#include <cuda_runtime.h>
#include <cuda_bf16.h>

#define NB    8
#define NC    512
#define NPIX  4096      // 64*64
#define NCLS  19
#define TGT   512
#define NSPLIT 16
#define CSPAN (NC/NSPLIT)   // 32
#define K3_T  256
#define PXB   (K3_T*2)      // 512 pixels per K3 block
#define NTILE (NPIX/PXB)    // 8
#define NROW  (NB*NC*2)     // 8192 channel-rows (S then T)

// ---------------- device scratch (static, no allocations) ----------------
__device__ unsigned char g_lab[NB*NPIX];
__device__ float g_cnt [NB*NCLS];
__device__ float g_sumS[NB*NC*NCLS];
__device__ float g_sumT[NB*NC*NCLS];
__device__ float g_nsqS[NB*NCLS];
__device__ float g_nsqT[NB*NCLS];
__device__ float g_accum[4][NB*NPIX];   // dotS,fsqS,dotT,fsqT (atomics)
__device__ float g_blockred[128];

// ---- K0: labels + histogram (blocks 0..7) and accumulator zeroing (8..39) --
__global__ void k_prep(const int* __restrict__ tgt) {
    int blk = blockIdx.x;
    if (blk >= NB) {
        // zero g_accum: 32 blocks * 256 threads * 4 float4 = 512 KB
        int z = (blk - NB)*256 + threadIdx.x;      // 0..8191
        float4* p = (float4*)g_accum;               // 32768 float4 total
        #pragma unroll
        for (int j = 0; j < 4; j++) p[z*4 + j] = make_float4(0.f,0.f,0.f,0.f);
        return;
    }
    int b = blk;
    __shared__ int hist[NCLS];
    if (threadIdx.x < NCLS) hist[threadIdx.x] = 0;
    __syncthreads();
    for (int n = threadIdx.x; n < NPIX; n += blockDim.x) {
        int h = n >> 6, w = n & 63;
        int k = tgt[b*TGT*TGT + (h*8)*TGT + (w*8)];   // nearest: idx*8
        unsigned char lab = (k >= 0 && k < NCLS) ? (unsigned char)k : (unsigned char)255;
        g_lab[b*NPIX + n] = lab;
        if (lab != 255) atomicAdd(&hist[k], 1);
    }
    __syncthreads();
    if (threadIdx.x < NCLS) g_cnt[b*NCLS + threadIdx.x] = (float)hist[threadIdx.x];
}

// ---------------- K1: warp-per-channel class sums, lane-private bins ------
// bins[w][k][lane]: bank = lane -> conflict-free, no atomics, no barriers.
__global__ __launch_bounds__(256) void k_classsum(const float* __restrict__ S,
                                                  const float* __restrict__ T) {
    __shared__ float bins[8][NCLS+1][32];   // slot NCLS = trash for invalid labels
    int t    = threadIdx.x;
    int w    = t >> 5;
    int lane = t & 31;

    int r = blockIdx.x * 8 + w;          // 0..NROW-1
    int tensor = r >> 12;                // 0 = S, 1 = T
    int bc = r & (NB*NC - 1);
    int b  = bc >> 9;
    const float* F = tensor ? T : S;
    float* outp    = tensor ? g_sumT : g_sumS;

    #pragma unroll
    for (int k = 0; k <= NCLS; k++) bins[w][k][lane] = 0.f;

    const float4* row = (const float4*)(F + (size_t)bc * NPIX);
    const uchar4* lb  = (const uchar4*)&g_lab[b*NPIX];
    float* mb = &bins[w][0][lane];

    #pragma unroll 4
    for (int i = lane; i < NPIX/4; i += 32) {
        float4 v = row[i];
        uchar4 l = lb[i];
        int kx = l.x < NCLS ? l.x : NCLS;
        int ky = l.y < NCLS ? l.y : NCLS;
        int kz = l.z < NCLS ? l.z : NCLS;
        int kw = l.w < NCLS ? l.w : NCLS;
        mb[32*kx] += v.x;
        mb[32*ky] += v.y;
        mb[32*kz] += v.z;
        mb[32*kw] += v.w;
    }
    __syncwarp();

    size_t ob = (size_t)bc * NCLS;
    #pragma unroll
    for (int k = 0; k < NCLS; k++) {
        float v = bins[w][k][lane];
        #pragma unroll
        for (int o = 16; o > 0; o >>= 1) v += __shfl_down_sync(0xFFFFFFFFu, v, o);
        if (lane == 0) outp[ob + k] = v;
    }
}

// ---------------- K2: per-(b,k) squared norm of class sums ----------------
__global__ void k_stats() {
    int b = blockIdx.x, k = blockIdx.y, t = threadIdx.x;
    float aS = 0.f, aT = 0.f;
    for (int c = t; c < NC; c += 256) {
        float s = g_sumS[((size_t)b*NC + c)*NCLS + k]; aS += s*s;
        float u = g_sumT[((size_t)b*NC + c)*NCLS + k]; aT += u*u;
    }
    #pragma unroll
    for (int o = 16; o > 0; o >>= 1) {
        aS += __shfl_down_sync(0xFFFFFFFFu, aS, o);
        aT += __shfl_down_sync(0xFFFFFFFFu, aT, o);
    }
    __shared__ float sS[8], sT[8];
    if ((t & 31) == 0) { sS[t >> 5] = aS; sT[t >> 5] = aT; }
    __syncthreads();
    if (t == 0) {
        float s = 0.f, u = 0.f;
        #pragma unroll
        for (int w = 0; w < 8; w++) { s += sS[w]; u += sT[w]; }
        g_nsqS[b*NCLS + k] = s;
        g_nsqT[b*NCLS + k] = u;
    }
}

// ---------------- K3: main pass, ONE tensor per block ---------------------
// z = sp*2 + tensor -> grid 2048 (13.8/SM). 8 accumulators/thread, 1 LDG +
// 2 LDS + 4 FFMA per channel. Epilogue: REDG atomics.
__global__ __launch_bounds__(K3_T) void k_main(const float* __restrict__ S,
                                               const float* __restrict__ T) {
    int tile = blockIdx.x;           // 0..NTILE-1
    int b    = blockIdx.y;           // 0..7
    int zz   = blockIdx.z;           // 0..31
    int tensor = zz & 1;
    int sp     = zz >> 1;
    __shared__ float sh[CSPAN*NCLS];     // 32*19 = 608 floats
    int t = threadIdx.x;
    int c0 = sp*CSPAN;

    const float* F  = tensor ? T : S;
    const float* gs = tensor ? g_sumT : g_sumS;
    float* accD = tensor ? g_accum[2] : g_accum[0];
    float* accF = tensor ? g_accum[3] : g_accum[1];

    for (int i = t; i < CSPAN*NCLS; i += K3_T)
        sh[i] = gs[((size_t)(b*NC + c0))*NCLS + i];
    int px = tile*PXB + 2*t;
    unsigned char lx = g_lab[b*NPIX + px];
    unsigned char ly = g_lab[b*NPIX + px + 1];
    int k0 = (lx < NCLS) ? lx : 0;   // dot unused for invalid labels
    int k1 = (ly < NCLS) ? ly : 0;
    __syncthreads();

    const float2* pF = (const float2*)(F + ((size_t)(b*NC + c0))*NPIX + px);

    float d0=0,d1=0, f0=0,f1=0;
    #pragma unroll 8
    for (int c = 0; c < CSPAN; c++) {
        float2 v = pF[c*(NPIX/2)];
        float mA = sh[c*NCLS + k0], mB = sh[c*NCLS + k1];
        f0 += v.x*v.x;  d0 += v.x*mA;
        f1 += v.y*v.y;  d1 += v.y*mB;
    }
    int gi = b*NPIX + px;
    atomicAdd(&accD[gi],   d0);
    atomicAdd(&accD[gi+1], d1);
    atomicAdd(&accF[gi],   f0);
    atomicAdd(&accF[gi+1], f1);
}

// ---------------- K4: cosine sims + per-block MSE partial (L2 reads) ------
__global__ void k_final() {
    int t = threadIdx.x;
    int gi = blockIdx.x*256 + t;   // 128 blocks * 256 = 32768 pixels
    float dS = g_accum[0][gi];
    float fS = g_accum[1][gi];
    float dT = g_accum[2][gi];
    float fT = g_accum[3][gi];
    int b = gi >> 12;
    int k = g_lab[gi];
    float pS_, pT_;
    if (k < NCLS) {
        float cnt = g_cnt[b*NCLS + k];
        float inv = 1.f/(cnt + 1e-6f);
        float nfS = sqrtf(fS);
        float nmS = sqrtf(g_nsqS[b*NCLS + k]) * inv;
        pS_ = (dS*inv) / (fmaxf(nfS, 1e-8f) * fmaxf(nmS, 1e-8f));
        float nfT = sqrtf(fT);
        float nmT = sqrtf(g_nsqT[b*NCLS + k]) * inv;
        pT_ = (dT*inv) / (fmaxf(nfT, 1e-8f) * fmaxf(nmT, 1e-8f));
    } else {
        // invalid label: center = f  ->  cos(f, f)
        float nfS = fmaxf(sqrtf(fS), 1e-8f); pS_ = fS/(nfS*nfS);
        float nfT = fmaxf(sqrtf(fT), 1e-8f); pT_ = fT/(nfT*nfT);
    }
    float d = pS_ - pT_;
    float v = d*d;
    #pragma unroll
    for (int o = 16; o > 0; o >>= 1) v += __shfl_down_sync(0xFFFFFFFFu, v, o);
    __shared__ float sw[8];
    if ((t & 31) == 0) sw[t >> 5] = v;
    __syncthreads();
    if (t == 0) {
        float a = 0.f;
        #pragma unroll
        for (int w = 0; w < 8; w++) a += sw[w];
        g_blockred[blockIdx.x] = a;
    }
}

// ---------------- K5: final deterministic reduction to scalar -------------
__global__ void k_out(float* __restrict__ out) {
    int t = threadIdx.x;   // 128 threads
    float v = g_blockred[t];
    #pragma unroll
    for (int o = 16; o > 0; o >>= 1) v += __shfl_down_sync(0xFFFFFFFFu, v, o);
    __shared__ float s[4];
    if ((t & 31) == 0) s[t >> 5] = v;
    __syncthreads();
    if (t == 0) out[0] = (s[0] + s[1] + s[2] + s[3]) * (1.f/32768.f);
}

extern "C" void kernel_launch(void* const* d_in, const int* in_sizes, int n_in,
                              void* d_out, int out_size) {
    const float* S   = (const float*)d_in[0];
    const float* T   = (const float*)d_in[1];
    const int*   tgt = (const int*)d_in[2];
    float* out = (float*)d_out;

    k_prep    <<<NB + 32, 256>>>(tgt);
    k_classsum<<<NROW/8, 256>>>(S, T);
    k_stats   <<<dim3(NB, NCLS), 256>>>();
    k_main    <<<dim3(NTILE, NB, NSPLIT*2), K3_T>>>(S, T);
    k_final   <<<128, 256>>>();
    k_out     <<<1, 128>>>(out);
}